// round 5
// baseline (speedup 1.0000x reference)
#include <cuda_runtime.h>
#include <math.h>

#define NTOK 16384
#define DDIM 1024
#define HDIM 4096
#define NEXP 8
#define PROJD 256
#define CAP 12288
#define CLAMP_MAXV 4.605170185988091f  /* log(1/0.01) */

#define BM 128
#define BN 128
#define BK 8
#define TM 8
#define TN 8

// ---------------- device scratch (no cudaMalloc allowed) ----------------
__device__ float g_P[NTOK * PROJD];                       // 16 MB
__device__ float g_simn[PROJD * NEXP];
__device__ int   g_perm[NEXP * CAP];
__device__ int   g_pos[NTOK * 2];
__device__ float g_gate[NTOK * 2];
__device__ int   g_cursor[NEXP];
__device__ float g_H[(size_t)NEXP * CAP * HDIM];          // 1.5 GiB
__device__ float g_F[(size_t)NEXP * CAP * DDIM];          // 384 MiB

// ---------------- small kernels ----------------
__global__ void init_kernel() {
    if (threadIdx.x < NEXP) g_cursor[threadIdx.x] = 0;
}

__global__ void simn_kernel(const float* __restrict__ sim) {
    int e = threadIdx.x;
    if (e < NEXP) {
        float s = 0.f;
        for (int j = 0; j < PROJD; j++) { float v = sim[j * NEXP + e]; s += v * v; }
        float inv = 1.f / fmaxf(sqrtf(s), 1e-12f);
        for (int j = 0; j < PROJD; j++) g_simn[j * NEXP + e] = sim[j * NEXP + e] * inv;
    }
}

// one warp per token: l2norm(P row), logits = projn @ simn * scale, top-2, softmax, route
__global__ void gating_kernel(const float* __restrict__ P,
                              const float* __restrict__ temp) {
    __shared__ float ssim[PROJD * NEXP];
    for (int i = threadIdx.x; i < PROJD * NEXP; i += blockDim.x) ssim[i] = g_simn[i];
    __syncthreads();

    int tok  = (blockIdx.x * blockDim.x + threadIdx.x) >> 5;
    int lane = threadIdx.x & 31;
    if (tok >= NTOK) return;

    const float* row = P + (size_t)tok * PROJD;
    float dot[NEXP];
#pragma unroll
    for (int e = 0; e < NEXP; e++) dot[e] = 0.f;
    float ss = 0.f;
#pragma unroll
    for (int i = 0; i < PROJD / 32; i++) {
        float p = row[lane + 32 * i];
        ss += p * p;
        const float* sr = ssim + (lane + 32 * i) * NEXP;
#pragma unroll
        for (int e = 0; e < NEXP; e++) dot[e] += p * sr[e];
    }
#pragma unroll
    for (int off = 16; off; off >>= 1) {
        ss += __shfl_down_sync(0xffffffffu, ss, off);
#pragma unroll
        for (int e = 0; e < NEXP; e++) dot[e] += __shfl_down_sync(0xffffffffu, dot[e], off);
    }
    if (lane == 0) {
        float scale = expf(fminf(temp[0], CLAMP_MAXV));
        float inv = 1.f / fmaxf(sqrtf(ss), 1e-12f);
        float lg[NEXP];
#pragma unroll
        for (int e = 0; e < NEXP; e++) lg[e] = dot[e] * inv * scale;
        int e0 = 0;
#pragma unroll
        for (int e = 1; e < NEXP; e++) if (lg[e] > lg[e0]) e0 = e;
        int e1 = (e0 == 0) ? 1 : 0;
#pragma unroll
        for (int e = 0; e < NEXP; e++) if (e != e0 && lg[e] > lg[e1]) e1 = e;
        float ex = expf(lg[e1] - lg[e0]);
        float den = 1.f + ex;
        float g0 = 1.f / den;
        float g1 = ex / den;
        int p0 = atomicAdd(&g_cursor[e0], 1); p0 = min(p0, CAP - 1);
        g_perm[e0 * CAP + p0] = tok;
        g_pos[tok * 2 + 0] = e0 * CAP + p0;
        g_gate[tok * 2 + 0] = g0;
        int p1 = atomicAdd(&g_cursor[e1], 1); p1 = min(p1, CAP - 1);
        g_perm[e1 * CAP + p1] = tok;
        g_pos[tok * 2 + 1] = e1 * CAP + p1;
        g_gate[tok * 2 + 1] = g1;
    }
}

// ---------------- generic tiled SGEMM ----------------
// MODE 0: C[M=NTOK,N] = A @ B + bias                        (gating proj)
// MODE 1: H[z-seg]    = gelu(x[perm] @ W1[z] + b1[z])       (expert up-proj)
// MODE 2: F[z-seg]    = H[z-seg] @ W2[z] + b2[z]            (expert down-proj)
template <int MODE>
__global__ __launch_bounds__(256, 2)
void sgemm(const float* __restrict__ A,
           const float* __restrict__ Bw,
           const float* __restrict__ bias,
           float* __restrict__ C,
           const int* __restrict__ perm,
           const int* __restrict__ counts,
           int K, int N) {
    const int z  = blockIdx.z;
    const int mt = blockIdx.y;
    const int nt = blockIdx.x;
    const int M = (MODE == 0) ? NTOK : min(counts[z], CAP);
    if (mt * BM >= M) return;

    __shared__ float As[BK][BM];
    __shared__ float Bs[BK][BN];

    const int tid  = threadIdx.x;
    const int aRow = tid >> 1;
    const int aK   = (tid & 1) * 4;
    const int bK   = tid >> 5;
    const int bN   = (tid & 31) * 4;

    const int rowg = mt * BM + aRow;
    const bool aValid = rowg < M;
    const float* aPtr = A;
    if (aValid) {
        size_t roff;
        if (MODE == 1)      roff = (size_t)perm[(size_t)z * CAP + rowg] * (size_t)K;
        else if (MODE == 2) roff = ((size_t)z * CAP + rowg) * (size_t)K;
        else                roff = (size_t)rowg * (size_t)K;
        aPtr = A + roff + aK;
    }
    const float* bPtr = Bw + (MODE ? (size_t)z * K * N : (size_t)0)
                        + (size_t)bK * N + (size_t)nt * BN + bN;

    const int tr = tid >> 4;   // 0..15
    const int tc = tid & 15;   // 0..15

    float acc[TM][TN];
#pragma unroll
    for (int i = 0; i < TM; i++)
#pragma unroll
        for (int j = 0; j < TN; j++) acc[i][j] = 0.f;

    float4 ra = aValid ? *(const float4*)aPtr : make_float4(0.f, 0.f, 0.f, 0.f);
    float4 rb = *(const float4*)bPtr;

    const int nk = K / BK;
    for (int kt = 0; kt < nk; kt++) {
        As[aK + 0][aRow] = ra.x;
        As[aK + 1][aRow] = ra.y;
        As[aK + 2][aRow] = ra.z;
        As[aK + 3][aRow] = ra.w;
        *(float4*)&Bs[bK][bN] = rb;
        __syncthreads();
        if (kt + 1 < nk) {
            if (aValid) ra = *(const float4*)(aPtr + (size_t)(kt + 1) * BK);
            rb = *(const float4*)(bPtr + (size_t)(kt + 1) * BK * N);
        }
#pragma unroll
        for (int k = 0; k < BK; k++) {
            float4 a0 = *(const float4*)&As[k][tr * TM];
            float4 a1 = *(const float4*)&As[k][tr * TM + 4];
            float4 b0 = *(const float4*)&Bs[k][tc * TN];
            float4 b1 = *(const float4*)&Bs[k][tc * TN + 4];
            float ar[8] = {a0.x, a0.y, a0.z, a0.w, a1.x, a1.y, a1.z, a1.w};
            float br[8] = {b0.x, b0.y, b0.z, b0.w, b1.x, b1.y, b1.z, b1.w};
#pragma unroll
            for (int i = 0; i < TM; i++)
#pragma unroll
                for (int j = 0; j < TN; j++) acc[i][j] += ar[i] * br[j];
        }
        __syncthreads();
    }

    const float* bs = bias + (MODE ? (size_t)z * N : (size_t)0) + nt * BN + tc * TN;
    float bv[TN];
#pragma unroll
    for (int j = 0; j < TN; j++) bv[j] = bs[j];

#pragma unroll
    for (int i = 0; i < TM; i++) {
        int row = mt * BM + tr * TM + i;
        if (row < M) {
            size_t coff;
            if (MODE == 0) coff = (size_t)row * N;
            else           coff = ((size_t)z * CAP + row) * (size_t)N;
            float* cp = C + coff + (size_t)nt * BN + tc * TN;
#pragma unroll
            for (int j = 0; j < TN; j++) {
                float v = acc[i][j] + bv[j];
                if (MODE == 1) v = 0.5f * v * (1.0f + erff(v * 0.70710678118654752f));
                cp[j] = v;
            }
        }
    }
}

// out = x + g0 * F[pos0] + g1 * F[pos1]
__global__ void final_kernel(const float* __restrict__ x, float* __restrict__ out) {
    int idx = blockIdx.x * blockDim.x + threadIdx.x;   // over NTOK*DDIM/4
    int n = idx >> 8;          // DDIM/4 = 256
    int c = idx & 255;
    float4 xv = ((const float4*)x)[idx];
    int p0 = g_pos[n * 2], p1 = g_pos[n * 2 + 1];
    float gg0 = g_gate[n * 2], gg1 = g_gate[n * 2 + 1];
    const float4* F4 = (const float4*)g_F;
    float4 f0 = F4[(size_t)p0 * 256 + c];
    float4 f1 = F4[(size_t)p1 * 256 + c];
    float4 o;
    o.x = xv.x + gg0 * f0.x + gg1 * f1.x;
    o.y = xv.y + gg0 * f0.y + gg1 * f1.y;
    o.z = xv.z + gg0 * f0.z + gg1 * f1.z;
    o.w = xv.w + gg0 * f0.w + gg1 * f1.w;
    ((float4*)out)[idx] = o;
}

// ---------------- launch ----------------
extern "C" void kernel_launch(void* const* d_in, const int* in_sizes, int n_in,
                              void* d_out, int out_size) {
    const float* x    = (const float*)d_in[0];
    const float* Wp   = (const float*)d_in[1];
    const float* bp   = (const float*)d_in[2];
    const float* sim  = (const float*)d_in[3];
    const float* temp = (const float*)d_in[4];
    const float* W1   = (const float*)d_in[5];
    const float* b1   = (const float*)d_in[6];
    const float* W2   = (const float*)d_in[7];
    const float* b2   = (const float*)d_in[8];
    float* out = (float*)d_out;

    void *pP = nullptr, *pH = nullptr, *pF = nullptr, *pPerm = nullptr, *pCur = nullptr;
    cudaGetSymbolAddress(&pP, g_P);
    cudaGetSymbolAddress(&pH, g_H);
    cudaGetSymbolAddress(&pF, g_F);
    cudaGetSymbolAddress(&pPerm, g_perm);
    cudaGetSymbolAddress(&pCur, g_cursor);

    init_kernel<<<1, 32>>>();
    simn_kernel<<<1, 32>>>(sim);

    // P = x @ Wp + bp
    sgemm<0><<<dim3(PROJD / BN, NTOK / BM, 1), 256>>>(
        x, Wp, bp, (float*)pP, nullptr, nullptr, DDIM, PROJD);

    gating_kernel<<<(NTOK * 32) / 256, 256>>>((const float*)pP, temp);

    // H = gelu(x[perm] @ W1[e] + b1[e])
    sgemm<1><<<dim3(HDIM / BN, CAP / BM, NEXP), 256>>>(
        x, W1, b1, (float*)pH, (const int*)pPerm, (const int*)pCur, DDIM, HDIM);

    // F = H @ W2[e] + b2[e]
    sgemm<2><<<dim3(DDIM / BN, CAP / BM, NEXP), 256>>>(
        (const float*)pH, W2, b2, (float*)pF, nullptr, (const int*)pCur, HDIM, DDIM);

    final_kernel<<<(NTOK * DDIM / 4) / 256, 256>>>(x, out);
}

// round 10
// speedup vs baseline: 2.2698x; 2.2698x over previous
#include <cuda_runtime.h>
#include <cuda_bf16.h>
#include <math.h>

#define NTOK 16384
#define DDIM 1024
#define HDIM 4096
#define NEXP 8
#define PROJD 256
#define CAP 12288
#define CLAMP_MAXV 4.605170185988091f

#define BMT 128
#define BNT 128
#define BKT 16
#define OFF_AHI 0
#define OFF_ALO 4096
#define OFF_BHI 8192
#define OFF_BLO 12288
#define STAGE 16384

// ---------------- device scratch ----------------
__device__ float g_P[NTOK * PROJD];
__device__ float g_simn[PROJD * NEXP];
__device__ int   g_perm[NEXP * CAP];
__device__ int   g_pos[NTOK * 2];
__device__ float g_gate[NTOK * 2];
__device__ int   g_cursor[NEXP];
__device__ __nv_bfloat16 g_xhi[(size_t)NTOK * DDIM];
__device__ __nv_bfloat16 g_xlo[(size_t)NTOK * DDIM];
__device__ __nv_bfloat16 g_w1thi[(size_t)NEXP * HDIM * DDIM];
__device__ __nv_bfloat16 g_w1tlo[(size_t)NEXP * HDIM * DDIM];
__device__ __nv_bfloat16 g_w2thi[(size_t)NEXP * DDIM * HDIM];
__device__ __nv_bfloat16 g_w2tlo[(size_t)NEXP * DDIM * HDIM];
__device__ __nv_bfloat16 g_Hhi[(size_t)NEXP * CAP * HDIM];
__device__ __nv_bfloat16 g_Hlo[(size_t)NEXP * CAP * HDIM];
__device__ float g_F[(size_t)NEXP * CAP * DDIM];

// ---------------- helpers ----------------
__device__ __forceinline__ unsigned smem_u32(const void* p) {
    unsigned a;
    asm("{ .reg .u64 t; cvta.to.shared.u64 t, %1; cvt.u32.u64 %0, t; }" : "=r"(a) : "l"(p));
    return a;
}
#define CPA(dst, src) asm volatile("cp.async.cg.shared.global [%0], [%1], 16;" :: "r"(dst), "l"(src))
#define CPA_COMMIT()  asm volatile("cp.async.commit_group;" ::: "memory")
#define CPA_WAIT1()   asm volatile("cp.async.wait_group 1;" ::: "memory")
#define CPA_WAIT0()   asm volatile("cp.async.wait_group 0;" ::: "memory")
#define LDSM4(R, A) asm volatile("ldmatrix.sync.aligned.m8n8.x4.shared.b16 {%0,%1,%2,%3}, [%4];" \
    : "=r"((R)[0]), "=r"((R)[1]), "=r"((R)[2]), "=r"((R)[3]) : "r"(A))

__device__ __forceinline__ void mma16816(float* c, const unsigned* a, const unsigned* b) {
    asm volatile(
        "mma.sync.aligned.m16n8k16.row.col.f32.bf16.bf16.f32 "
        "{%0,%1,%2,%3}, {%4,%5,%6,%7}, {%8,%9}, {%0,%1,%2,%3};"
        : "+f"(c[0]), "+f"(c[1]), "+f"(c[2]), "+f"(c[3])
        : "r"(a[0]), "r"(a[1]), "r"(a[2]), "r"(a[3]), "r"(b[0]), "r"(b[1]));
}
__device__ __forceinline__ void split2(float v, unsigned short& h, unsigned short& l) {
    __nv_bfloat16 bh = __float2bfloat16(v);
    __nv_bfloat16 bl = __float2bfloat16(v - __bfloat162float(bh));
    h = __bfloat16_as_ushort(bh); l = __bfloat16_as_ushort(bl);
}
// 32B rows, 16B-chunk XOR swizzle: conflict-free for 8-row ldmatrix
__device__ __forceinline__ unsigned swz(int row, int chunk) {
    return (unsigned)(row * 32 + ((chunk ^ ((row >> 2) & 1)) << 4));
}

// ---------------- small kernels ----------------
__global__ void init_kernel() { if (threadIdx.x < NEXP) g_cursor[threadIdx.x] = 0; }

__global__ void simn_kernel(const float* __restrict__ sim) {
    int e = threadIdx.x;
    if (e < NEXP) {
        float s = 0.f;
        for (int j = 0; j < PROJD; j++) { float v = sim[j * NEXP + e]; s += v * v; }
        float inv = 1.f / fmaxf(sqrtf(s), 1e-12f);
        for (int j = 0; j < PROJD; j++) g_simn[j * NEXP + e] = sim[j * NEXP + e] * inv;
    }
}

__global__ void gating_kernel(const float* __restrict__ P, const float* __restrict__ temp) {
    __shared__ float ssim[PROJD * NEXP];
    for (int i = threadIdx.x; i < PROJD * NEXP; i += blockDim.x) ssim[i] = g_simn[i];
    __syncthreads();
    int tok = (blockIdx.x * blockDim.x + threadIdx.x) >> 5;
    int lane = threadIdx.x & 31;
    if (tok >= NTOK) return;
    const float* row = P + (size_t)tok * PROJD;
    float dot[NEXP];
#pragma unroll
    for (int e = 0; e < NEXP; e++) dot[e] = 0.f;
    float ss = 0.f;
#pragma unroll
    for (int i = 0; i < PROJD / 32; i++) {
        float p = row[lane + 32 * i];
        ss += p * p;
        const float* sr = ssim + (lane + 32 * i) * NEXP;
#pragma unroll
        for (int e = 0; e < NEXP; e++) dot[e] += p * sr[e];
    }
#pragma unroll
    for (int off = 16; off; off >>= 1) {
        ss += __shfl_down_sync(0xffffffffu, ss, off);
#pragma unroll
        for (int e = 0; e < NEXP; e++) dot[e] += __shfl_down_sync(0xffffffffu, dot[e], off);
    }
    if (lane == 0) {
        float scale = expf(fminf(temp[0], CLAMP_MAXV));
        float inv = 1.f / fmaxf(sqrtf(ss), 1e-12f);
        float lg[NEXP];
#pragma unroll
        for (int e = 0; e < NEXP; e++) lg[e] = dot[e] * inv * scale;
        int e0 = 0;
#pragma unroll
        for (int e = 1; e < NEXP; e++) if (lg[e] > lg[e0]) e0 = e;
        int e1 = (e0 == 0) ? 1 : 0;
#pragma unroll
        for (int e = 0; e < NEXP; e++) if (e != e0 && lg[e] > lg[e1]) e1 = e;
        float ex = expf(lg[e1] - lg[e0]);
        float den = 1.f + ex;
        int p0 = atomicAdd(&g_cursor[e0], 1); p0 = min(p0, CAP - 1);
        g_perm[e0 * CAP + p0] = tok;
        g_pos[tok * 2 + 0] = e0 * CAP + p0;
        g_gate[tok * 2 + 0] = 1.f / den;
        int p1 = atomicAdd(&g_cursor[e1], 1); p1 = min(p1, CAP - 1);
        g_perm[e1 * CAP + p1] = tok;
        g_pos[tok * 2 + 1] = e1 * CAP + p1;
        g_gate[tok * 2 + 1] = ex / den;
    }
}

__global__ void conv_split_kernel(const float* __restrict__ src, int n4) {
    int i = blockIdx.x * blockDim.x + threadIdx.x;
    if (i >= n4) return;
    float4 v = ((const float4*)src)[i];
    float f[4] = {v.x, v.y, v.z, v.w};
    unsigned short h[4], l[4];
#pragma unroll
    for (int j = 0; j < 4; j++) split2(f[j], h[j], l[j]);
    ((uint2*)g_xhi)[i] = make_uint2(h[0] | (h[1] << 16), h[2] | (h[3] << 16));
    ((uint2*)g_xlo)[i] = make_uint2(l[0] | (l[1] << 16), l[2] | (l[3] << 16));
}

// W [E][R][C] -> Thi/Tlo [E][C][R]   (Thi/Tlo MUST be device addresses from cudaGetSymbolAddress)
__global__ void conv_wt_kernel(const float* __restrict__ W, __nv_bfloat16* __restrict__ Thi,
                               __nv_bfloat16* __restrict__ Tlo, int R, int C) {
    __shared__ float tile[32][33];
    int e = blockIdx.z, r0 = blockIdx.y * 32, c0 = blockIdx.x * 32;
    const float* Wp = W + (size_t)e * R * C;
    for (int i = threadIdx.y; i < 32; i += 8)
        tile[i][threadIdx.x] = Wp[(size_t)(r0 + i) * C + c0 + threadIdx.x];
    __syncthreads();
    for (int i = threadIdx.y; i < 32; i += 8) {
        unsigned short h, l;
        split2(tile[threadIdx.x][i], h, l);
        size_t o = ((size_t)e * C + c0 + i) * R + r0 + threadIdx.x;
        Thi[o] = __ushort_as_bfloat16(h); Tlo[o] = __ushort_as_bfloat16(l);
    }
}

// fp32 SGEMM for gating projection (exact selection)
__global__ __launch_bounds__(256, 2)
void gemm_p(const float* __restrict__ A, const float* __restrict__ Bw,
            const float* __restrict__ bias, float* __restrict__ C) {
    const int K = DDIM, N = PROJD;
    const int mt = blockIdx.y, nt = blockIdx.x;
    __shared__ float As[8][128], Bs[8][128];
    const int tid = threadIdx.x;
    const int aRow = tid >> 1, aK = (tid & 1) * 4;
    const int bK = tid >> 5, bN = (tid & 31) * 4;
    const float* aPtr = A + (size_t)(mt * 128 + aRow) * K + aK;
    const float* bPtr = Bw + (size_t)bK * N + nt * 128 + bN;
    const int tr = tid >> 4, tc = tid & 15;
    float acc[8][8];
#pragma unroll
    for (int i = 0; i < 8; i++)
#pragma unroll
        for (int j = 0; j < 8; j++) acc[i][j] = 0.f;
    float4 ra = *(const float4*)aPtr;
    float4 rb = *(const float4*)bPtr;
    for (int kt = 0; kt < K / 8; kt++) {
        As[aK][aRow] = ra.x; As[aK + 1][aRow] = ra.y; As[aK + 2][aRow] = ra.z; As[aK + 3][aRow] = ra.w;
        *(float4*)&Bs[bK][bN] = rb;
        __syncthreads();
        if (kt + 1 < K / 8) {
            ra = *(const float4*)(aPtr + (size_t)(kt + 1) * 8);
            rb = *(const float4*)(bPtr + (size_t)(kt + 1) * 8 * N);
        }
#pragma unroll
        for (int k = 0; k < 8; k++) {
            float4 a0 = *(const float4*)&As[k][tr * 8];
            float4 a1 = *(const float4*)&As[k][tr * 8 + 4];
            float4 b0 = *(const float4*)&Bs[k][tc * 8];
            float4 b1 = *(const float4*)&Bs[k][tc * 8 + 4];
            float ar[8] = {a0.x, a0.y, a0.z, a0.w, a1.x, a1.y, a1.z, a1.w};
            float br[8] = {b0.x, b0.y, b0.z, b0.w, b1.x, b1.y, b1.z, b1.w};
#pragma unroll
            for (int i = 0; i < 8; i++)
#pragma unroll
                for (int j = 0; j < 8; j++) acc[i][j] += ar[i] * br[j];
        }
        __syncthreads();
    }
#pragma unroll
    for (int i = 0; i < 8; i++) {
        float* cp = C + (size_t)(mt * 128 + tr * 8 + i) * N + nt * 128 + tc * 8;
#pragma unroll
        for (int j = 0; j < 8; j++) cp[j] = acc[i][j] + bias[nt * 128 + tc * 8 + j];
    }
}

// ---------------- HMMA grouped GEMM (bf16 hi/lo x3, fp32 acc, static 32KB smem) ----------------
template <int MODE>
__global__ void __launch_bounds__(256)
moe_mma(const float* __restrict__ bias) {
    constexpr int K  = (MODE == 1) ? DDIM : HDIM;
    constexpr int NB = (MODE == 1) ? HDIM : DDIM;
    constexpr int NK = K / BKT;
    const int z = blockIdx.z, mt = blockIdx.y, nt = blockIdx.x;
    const int cnt = min(g_cursor[z], CAP);
    if (mt * BMT >= cnt) return;

    __shared__ __align__(128) char smem[2 * STAGE];
    const unsigned sb = smem_u32(smem);
    const int tid = threadIdx.x, wid = tid >> 5, lane = tid & 31;

    // ---- load mapping: thread -> row tid>>1, 16B chunk tid&1 ----
    const int lrow = tid >> 1, lc = tid & 1;
    size_t aOff;
    if (MODE == 1) aOff = (size_t)g_perm[z * CAP + min(mt * BMT + lrow, cnt - 1)] * DDIM;
    else           aOff = ((size_t)z * CAP + min(mt * BMT + lrow, cnt - 1)) * (size_t)HDIM;
    const size_t bOff = ((size_t)z * NB + nt * BNT + lrow) * (size_t)K;
    const __nv_bfloat16* gAhi = (MODE == 1) ? g_xhi : g_Hhi;
    const __nv_bfloat16* gAlo = (MODE == 1) ? g_xlo : g_Hlo;
    const __nv_bfloat16* gBhi = (MODE == 1) ? g_w1thi : g_w2thi;
    const __nv_bfloat16* gBlo = (MODE == 1) ? g_w1tlo : g_w2tlo;
    const unsigned dsw = swz(lrow, lc);

#define LOADC(cc, ss) do { \
        const unsigned st_ = sb + (ss) * STAGE; \
        const int ke_ = (cc) * BKT + lc * 8; \
        CPA(st_ + OFF_AHI + dsw, gAhi + aOff + ke_); \
        CPA(st_ + OFF_ALO + dsw, gAlo + aOff + ke_); \
        CPA(st_ + OFF_BHI + dsw, gBhi + bOff + ke_); \
        CPA(st_ + OFF_BLO + dsw, gBlo + bOff + ke_); \
        CPA_COMMIT(); \
    } while (0)

    // ---- compute mapping ----
    const int m0 = (wid & 1) * 64;
    const int n0 = (wid >> 1) * 32;
    const int rA = ((lane >> 3) & 1) * 8 + (lane & 7);
    const int cA = lane >> 4;
    const int rB = (lane >> 4) * 8 + (lane & 7);
    const int cB = (lane >> 3) & 1;

    float acc[4][4][4];
#pragma unroll
    for (int f = 0; f < 4; f++)
#pragma unroll
        for (int g = 0; g < 4; g++)
#pragma unroll
            for (int q = 0; q < 4; q++) acc[f][g][q] = 0.f;

    LOADC(0, 0);
    for (int c = 0; c < NK; c++) {
        const int s = c & 1;
        if (c + 1 < NK) { LOADC(c + 1, s ^ 1); CPA_WAIT1(); }
        else CPA_WAIT0();
        __syncthreads();
        const unsigned st = sb + s * STAGE;
        unsigned ah[4][4], al[4][4], bh[4][2], bl[4][2];
#pragma unroll
        for (int f = 0; f < 4; f++) {
            const int row = m0 + f * 16 + rA;
            const unsigned ad = st + OFF_AHI + swz(row, cA);
            LDSM4(ah[f], ad);
            LDSM4(al[f], ad + (OFF_ALO - OFF_AHI));
        }
#pragma unroll
        for (int j = 0; j < 2; j++) {
            const int row = n0 + j * 16 + rB;
            const unsigned bd = st + OFF_BHI + swz(row, cB);
            unsigned q[4], p[4];
            LDSM4(q, bd);
            LDSM4(p, bd + (OFF_BLO - OFF_BHI));
            bh[2 * j][0] = q[0]; bh[2 * j][1] = q[1];
            bh[2 * j + 1][0] = q[2]; bh[2 * j + 1][1] = q[3];
            bl[2 * j][0] = p[0]; bl[2 * j][1] = p[1];
            bl[2 * j + 1][0] = p[2]; bl[2 * j + 1][1] = p[3];
        }
#pragma unroll
        for (int f = 0; f < 4; f++)
#pragma unroll
            for (int g = 0; g < 4; g++) {
                mma16816(acc[f][g], ah[f], bh[g]);
                mma16816(acc[f][g], ah[f], bl[g]);
                mma16816(acc[f][g], al[f], bh[g]);
            }
        __syncthreads();
    }

    // ---- epilogue ----
    const float* bptr = bias + (size_t)z * NB + nt * BNT;
#pragma unroll
    for (int f = 0; f < 4; f++) {
#pragma unroll
        for (int h = 0; h < 2; h++) {
            const int ml = m0 + f * 16 + (lane >> 2) + 8 * h;
            const int mg = mt * BMT + ml;
            if (mg < cnt) {
                const size_t rowg = (size_t)z * CAP + mg;
#pragma unroll
                for (int g = 0; g < 4; g++) {
                    const int nc = n0 + g * 8 + (lane & 3) * 2;
                    float v0 = acc[f][g][2 * h + 0] + __ldg(bptr + nc);
                    float v1 = acc[f][g][2 * h + 1] + __ldg(bptr + nc + 1);
                    if (MODE == 1) {
                        v0 = 0.5f * v0 * (1.0f + erff(v0 * 0.70710678118654752f));
                        v1 = 0.5f * v1 * (1.0f + erff(v1 * 0.70710678118654752f));
                        unsigned short h0, l0, h1, l1;
                        split2(v0, h0, l0); split2(v1, h1, l1);
                        *(unsigned*)(g_Hhi + rowg * HDIM + nt * BNT + nc) = (unsigned)h0 | ((unsigned)h1 << 16);
                        *(unsigned*)(g_Hlo + rowg * HDIM + nt * BNT + nc) = (unsigned)l0 | ((unsigned)l1 << 16);
                    } else {
                        *(float2*)(g_F + rowg * DDIM + nt * BNT + nc) = make_float2(v0, v1);
                    }
                }
            }
        }
    }
#undef LOADC
}

__global__ void final_kernel(const float* __restrict__ x, float* __restrict__ out) {
    int idx = blockIdx.x * blockDim.x + threadIdx.x;
    int n = idx >> 8, c = idx & 255;
    float4 xv = ((const float4*)x)[idx];
    int p0 = g_pos[n * 2], p1 = g_pos[n * 2 + 1];
    float gg0 = g_gate[n * 2], gg1 = g_gate[n * 2 + 1];
    const float4* F4 = (const float4*)g_F;
    float4 f0 = F4[(size_t)p0 * 256 + c];
    float4 f1 = F4[(size_t)p1 * 256 + c];
    ((float4*)out)[idx] = make_float4(xv.x + gg0 * f0.x + gg1 * f1.x,
                                      xv.y + gg0 * f0.y + gg1 * f1.y,
                                      xv.z + gg0 * f0.z + gg1 * f1.z,
                                      xv.w + gg0 * f0.w + gg1 * f1.w);
}

// ---------------- launch ----------------
extern "C" void kernel_launch(void* const* d_in, const int* in_sizes, int n_in,
                              void* d_out, int out_size) {
    const float* x    = (const float*)d_in[0];
    const float* Wp   = (const float*)d_in[1];
    const float* bp   = (const float*)d_in[2];
    const float* sim  = (const float*)d_in[3];
    const float* temp = (const float*)d_in[4];
    const float* W1   = (const float*)d_in[5];
    const float* b1   = (const float*)d_in[6];
    const float* W2   = (const float*)d_in[7];
    const float* b2   = (const float*)d_in[8];
    float* out = (float*)d_out;

    // device addresses for symbols used as HOST-passed kernel args
    void *pP = nullptr, *pw1h = nullptr, *pw1l = nullptr, *pw2h = nullptr, *pw2l = nullptr;
    cudaGetSymbolAddress(&pP, g_P);
    cudaGetSymbolAddress(&pw1h, g_w1thi);
    cudaGetSymbolAddress(&pw1l, g_w1tlo);
    cudaGetSymbolAddress(&pw2h, g_w2thi);
    cudaGetSymbolAddress(&pw2l, g_w2tlo);

    init_kernel<<<1, 32>>>();
    simn_kernel<<<1, 32>>>(sim);
    gemm_p<<<dim3(PROJD / 128, NTOK / 128), 256>>>(x, Wp, bp, (float*)pP);
    gating_kernel<<<(NTOK * 32) / 256, 256>>>((const float*)pP, temp);

    conv_split_kernel<<<(NTOK * DDIM / 4) / 256, 256>>>(x, NTOK * DDIM / 4);
    conv_wt_kernel<<<dim3(HDIM / 32, DDIM / 32, NEXP), dim3(32, 8)>>>(
        W1, (__nv_bfloat16*)pw1h, (__nv_bfloat16*)pw1l, DDIM, HDIM);
    conv_wt_kernel<<<dim3(DDIM / 32, HDIM / 32, NEXP), dim3(32, 8)>>>(
        W2, (__nv_bfloat16*)pw2h, (__nv_bfloat16*)pw2l, HDIM, DDIM);

    moe_mma<1><<<dim3(HDIM / BNT, CAP / BMT, NEXP), 256>>>(b1);
    moe_mma<2><<<dim3(DDIM / BNT, CAP / BMT, NEXP), 256>>>(b2);

    final_kernel<<<(NTOK * DDIM / 4) / 256, 256>>>(x, out);
}

// round 11
// speedup vs baseline: 4.8158x; 2.1217x over previous
#include <cuda_runtime.h>
#include <cuda_fp16.h>
#include <math.h>

#define NTOK 16384
#define DDIM 1024
#define HDIM 4096
#define NEXP 8
#define PROJD 256
#define CAP 12288
#define CLAMP_MAXV 4.605170185988091f

#define BMT 256
#define BNT 128
#define BKT 32
#define A_BYTES 16384        /* 256 rows * 64B */
#define B_BYTES 8192         /* 128 rows * 64B */
#define OFF_B A_BYTES
#define STAGE (A_BYTES + B_BYTES)   /* 24576 */

// ---------------- device scratch ----------------
__device__ float g_P[NTOK * PROJD];
__device__ float g_simn[PROJD * NEXP];
__device__ int   g_perm[NEXP * CAP];
__device__ int   g_pos[NTOK * 2];
__device__ float g_gate[NTOK * 2];
__device__ int   g_cursor[NEXP];
__device__ __half g_xh[(size_t)NTOK * DDIM];
__device__ __half g_w1t[(size_t)NEXP * HDIM * DDIM];   // [E][H][D]
__device__ __half g_w2t[(size_t)NEXP * DDIM * HDIM];   // [E][D][H]
__device__ __half g_Hh[(size_t)NEXP * CAP * HDIM];
__device__ float g_F[(size_t)NEXP * CAP * DDIM];

// ---------------- helpers ----------------
__device__ __forceinline__ unsigned smem_u32(const void* p) {
    unsigned a;
    asm("{ .reg .u64 t; cvta.to.shared.u64 t, %1; cvt.u32.u64 %0, t; }" : "=r"(a) : "l"(p));
    return a;
}
#define CPA(dst, src) asm volatile("cp.async.cg.shared.global [%0], [%1], 16;" :: "r"(dst), "l"(src))
#define CPA_COMMIT()  asm volatile("cp.async.commit_group;" ::: "memory")
#define CPA_WAIT1()   asm volatile("cp.async.wait_group 1;" ::: "memory")
#define CPA_WAIT0()   asm volatile("cp.async.wait_group 0;" ::: "memory")
#define LDSM4(R, A) asm volatile("ldmatrix.sync.aligned.m8n8.x4.shared.b16 {%0,%1,%2,%3}, [%4];" \
    : "=r"((R)[0]), "=r"((R)[1]), "=r"((R)[2]), "=r"((R)[3]) : "r"(A))

__device__ __forceinline__ void mma16816(float* c, const unsigned* a, const unsigned* b) {
    asm volatile(
        "mma.sync.aligned.m16n8k16.row.col.f32.f16.f16.f32 "
        "{%0,%1,%2,%3}, {%4,%5,%6,%7}, {%8,%9}, {%0,%1,%2,%3};"
        : "+f"(c[0]), "+f"(c[1]), "+f"(c[2]), "+f"(c[3])
        : "r"(a[0]), "r"(a[1]), "r"(a[2]), "r"(a[3]), "r"(b[0]), "r"(b[1]));
}
// rows of 32 fp16 = 64B = chunks 0..3 of 16B; packed 2 rows per 128B line,
// chunk XOR'd by line index -> 8 distinct bank-groups for any 8-row ldmatrix
__device__ __forceinline__ unsigned swa(int r, int ch) {
    return (unsigned)((r >> 1) * 128 + (r & 1) * 64 + ((ch ^ ((r >> 1) & 3)) << 4));
}

// ---------------- small kernels ----------------
__global__ void init_kernel() { if (threadIdx.x < NEXP) g_cursor[threadIdx.x] = 0; }

__global__ void simn_kernel(const float* __restrict__ sim) {
    int e = threadIdx.x;
    if (e < NEXP) {
        float s = 0.f;
        for (int j = 0; j < PROJD; j++) { float v = sim[j * NEXP + e]; s += v * v; }
        float inv = 1.f / fmaxf(sqrtf(s), 1e-12f);
        for (int j = 0; j < PROJD; j++) g_simn[j * NEXP + e] = sim[j * NEXP + e] * inv;
    }
}

__global__ void gating_kernel(const float* __restrict__ P, const float* __restrict__ temp) {
    __shared__ float ssim[PROJD * NEXP];
    for (int i = threadIdx.x; i < PROJD * NEXP; i += blockDim.x) ssim[i] = g_simn[i];
    __syncthreads();
    int tok = (blockIdx.x * blockDim.x + threadIdx.x) >> 5;
    int lane = threadIdx.x & 31;
    if (tok >= NTOK) return;
    const float* row = P + (size_t)tok * PROJD;
    float dot[NEXP];
#pragma unroll
    for (int e = 0; e < NEXP; e++) dot[e] = 0.f;
    float ss = 0.f;
#pragma unroll
    for (int i = 0; i < PROJD / 32; i++) {
        float p = row[lane + 32 * i];
        ss += p * p;
        const float* sr = ssim + (lane + 32 * i) * NEXP;
#pragma unroll
        for (int e = 0; e < NEXP; e++) dot[e] += p * sr[e];
    }
#pragma unroll
    for (int off = 16; off; off >>= 1) {
        ss += __shfl_down_sync(0xffffffffu, ss, off);
#pragma unroll
        for (int e = 0; e < NEXP; e++) dot[e] += __shfl_down_sync(0xffffffffu, dot[e], off);
    }
    if (lane == 0) {
        float scale = expf(fminf(temp[0], CLAMP_MAXV));
        float inv = 1.f / fmaxf(sqrtf(ss), 1e-12f);
        float lg[NEXP];
#pragma unroll
        for (int e = 0; e < NEXP; e++) lg[e] = dot[e] * inv * scale;
        int e0 = 0;
#pragma unroll
        for (int e = 1; e < NEXP; e++) if (lg[e] > lg[e0]) e0 = e;
        int e1 = (e0 == 0) ? 1 : 0;
#pragma unroll
        for (int e = 0; e < NEXP; e++) if (e != e0 && lg[e] > lg[e1]) e1 = e;
        float ex = expf(lg[e1] - lg[e0]);
        float den = 1.f + ex;
        int p0 = atomicAdd(&g_cursor[e0], 1); p0 = min(p0, CAP - 1);
        g_perm[e0 * CAP + p0] = tok;
        g_pos[tok * 2 + 0] = e0 * CAP + p0;
        g_gate[tok * 2 + 0] = 1.f / den;
        int p1 = atomicAdd(&g_cursor[e1], 1); p1 = min(p1, CAP - 1);
        g_perm[e1 * CAP + p1] = tok;
        g_pos[tok * 2 + 1] = e1 * CAP + p1;
        g_gate[tok * 2 + 1] = ex / den;
    }
}

__global__ void conv_x_kernel(const float* __restrict__ src, int n4) {
    int i = blockIdx.x * blockDim.x + threadIdx.x;
    if (i >= n4) return;
    float4 v = ((const float4*)src)[i];
    __half2 a = __floats2half2_rn(v.x, v.y);
    __half2 b = __floats2half2_rn(v.z, v.w);
    ((uint2*)g_xh)[i] = make_uint2(*(unsigned*)&a, *(unsigned*)&b);
}

// W [E][R][C] fp32 -> T [E][C][R] fp16  (T must be a cudaGetSymbolAddress pointer!)
__global__ void conv_wt_kernel(const float* __restrict__ W, __half* __restrict__ T, int R, int C) {
    __shared__ float tile[32][33];
    int e = blockIdx.z, r0 = blockIdx.y * 32, c0 = blockIdx.x * 32;
    const float* Wp = W + (size_t)e * R * C;
    for (int i = threadIdx.y; i < 32; i += 8)
        tile[i][threadIdx.x] = Wp[(size_t)(r0 + i) * C + c0 + threadIdx.x];
    __syncthreads();
    for (int i = threadIdx.y; i < 32; i += 8)
        T[((size_t)e * C + c0 + i) * R + r0 + threadIdx.x] = __float2half_rn(tile[threadIdx.x][i]);
}

// fp32 SGEMM for gating projection (exact selection)
__global__ __launch_bounds__(256, 2)
void gemm_p(const float* __restrict__ A, const float* __restrict__ Bw,
            const float* __restrict__ bias, float* __restrict__ C) {
    const int K = DDIM, N = PROJD;
    const int mt = blockIdx.y, nt = blockIdx.x;
    __shared__ float As[8][128], Bs[8][128];
    const int tid = threadIdx.x;
    const int aRow = tid >> 1, aK = (tid & 1) * 4;
    const int bK = tid >> 5, bN = (tid & 31) * 4;
    const float* aPtr = A + (size_t)(mt * 128 + aRow) * K + aK;
    const float* bPtr = Bw + (size_t)bK * N + nt * 128 + bN;
    const int tr = tid >> 4, tc = tid & 15;
    float acc[8][8];
#pragma unroll
    for (int i = 0; i < 8; i++)
#pragma unroll
        for (int j = 0; j < 8; j++) acc[i][j] = 0.f;
    float4 ra = *(const float4*)aPtr;
    float4 rb = *(const float4*)bPtr;
    for (int kt = 0; kt < K / 8; kt++) {
        As[aK][aRow] = ra.x; As[aK + 1][aRow] = ra.y; As[aK + 2][aRow] = ra.z; As[aK + 3][aRow] = ra.w;
        *(float4*)&Bs[bK][bN] = rb;
        __syncthreads();
        if (kt + 1 < K / 8) {
            ra = *(const float4*)(aPtr + (size_t)(kt + 1) * 8);
            rb = *(const float4*)(bPtr + (size_t)(kt + 1) * 8 * N);
        }
#pragma unroll
        for (int k = 0; k < 8; k++) {
            float4 a0 = *(const float4*)&As[k][tr * 8];
            float4 a1 = *(const float4*)&As[k][tr * 8 + 4];
            float4 b0 = *(const float4*)&Bs[k][tc * 8];
            float4 b1 = *(const float4*)&Bs[k][tc * 8 + 4];
            float ar[8] = {a0.x, a0.y, a0.z, a0.w, a1.x, a1.y, a1.z, a1.w};
            float br[8] = {b0.x, b0.y, b0.z, b0.w, b1.x, b1.y, b1.z, b1.w};
#pragma unroll
            for (int i = 0; i < 8; i++)
#pragma unroll
                for (int j = 0; j < 8; j++) acc[i][j] += ar[i] * br[j];
        }
        __syncthreads();
    }
#pragma unroll
    for (int i = 0; i < 8; i++) {
        float* cp = C + (size_t)(mt * 128 + tr * 8 + i) * N + nt * 128 + tc * 8;
#pragma unroll
        for (int j = 0; j < 8; j++) cp[j] = acc[i][j] + bias[nt * 128 + tc * 8 + j];
    }
}

// ---------------- HMMA grouped GEMM (fp16 single-pass, fp32 acc, 48KB static smem) ----------------
// MODE 1: H = gelu(x[perm] @ W1t^T + b1) -> fp16   MODE 2: F = H @ W2t^T + b2 -> fp32
template <int MODE>
__global__ void __launch_bounds__(256)
moe_mma(const float* __restrict__ bias) {
    constexpr int K  = (MODE == 1) ? DDIM : HDIM;
    constexpr int NB = (MODE == 1) ? HDIM : DDIM;
    constexpr int NK = K / BKT;
    const int z = blockIdx.z, mt = blockIdx.y, nt = blockIdx.x;
    const int cnt = min(g_cursor[z], CAP);
    if (mt * BMT >= cnt) return;

    __shared__ __align__(128) char smem[2 * STAGE];
    const unsigned sb = smem_u32(smem);
    const int tid = threadIdx.x, wid = tid >> 5, lane = tid & 31;

    // ---- load mapping: thread -> row tid>>1 (and +128 for A), 32B pair (tid&1) ----
    const int lrow = tid >> 1;
    const int chb = (tid & 1) * 2;           // chunk base 0 or 2
    size_t aOff0, aOff1;
    if (MODE == 1) {
        aOff0 = (size_t)g_perm[z * CAP + min(mt * BMT + lrow, cnt - 1)] * DDIM;
        aOff1 = (size_t)g_perm[z * CAP + min(mt * BMT + lrow + 128, cnt - 1)] * DDIM;
    } else {
        aOff0 = ((size_t)z * CAP + min(mt * BMT + lrow, cnt - 1)) * (size_t)HDIM;
        aOff1 = ((size_t)z * CAP + min(mt * BMT + lrow + 128, cnt - 1)) * (size_t)HDIM;
    }
    const size_t bOff = ((size_t)z * NB + nt * BNT + lrow) * (size_t)K;
    const __half* gA = (MODE == 1) ? g_xh : g_Hh;
    const __half* gB = (MODE == 1) ? g_w1t : g_w2t;
    const unsigned dA0a = swa(lrow, chb),       dA0b = swa(lrow, chb + 1);
    const unsigned dA1a = swa(lrow + 128, chb), dA1b = swa(lrow + 128, chb + 1);

#define LOADC(cc, ss) do { \
        const unsigned st_ = sb + (ss) * STAGE; \
        const int ke_ = (cc) * BKT + chb * 8; \
        CPA(st_ + dA0a, gA + aOff0 + ke_); \
        CPA(st_ + dA0b, gA + aOff0 + ke_ + 8); \
        CPA(st_ + dA1a, gA + aOff1 + ke_); \
        CPA(st_ + dA1b, gA + aOff1 + ke_ + 8); \
        CPA(st_ + OFF_B + dA0a, gB + bOff + ke_); \
        CPA(st_ + OFF_B + dA0b, gB + bOff + ke_ + 8); \
        CPA_COMMIT(); \
    } while (0)

    // ---- compute mapping: 8 warps as 4(M) x 2(N); warp tile 64x64 ----
    const int m0 = (wid & 3) * 64;
    const int n0 = (wid >> 2) * 64;
    const int rA = ((lane >> 3) & 1) * 8 + (lane & 7);
    const int cA = lane >> 4;
    const int rB = (lane >> 4) * 8 + (lane & 7);
    const int cB = (lane >> 3) & 1;

    float acc[4][8][4];
#pragma unroll
    for (int f = 0; f < 4; f++)
#pragma unroll
        for (int g = 0; g < 8; g++)
#pragma unroll
            for (int q = 0; q < 4; q++) acc[f][g][q] = 0.f;

    LOADC(0, 0);
    for (int c = 0; c < NK; c++) {
        const int s = c & 1;
        if (c + 1 < NK) { LOADC(c + 1, s ^ 1); CPA_WAIT1(); }
        else CPA_WAIT0();
        __syncthreads();
        const unsigned st = sb + s * STAGE;
#pragma unroll
        for (int kk = 0; kk < 2; kk++) {
            unsigned ah[4][4], bf[8][2];
#pragma unroll
            for (int f = 0; f < 4; f++)
                LDSM4(ah[f], st + swa(m0 + f * 16 + rA, kk * 2 + cA));
#pragma unroll
            for (int j = 0; j < 4; j++) {
                unsigned q[4];
                LDSM4(q, st + OFF_B + swa(n0 + j * 16 + rB, kk * 2 + cB));
                bf[2 * j][0] = q[0]; bf[2 * j][1] = q[1];
                bf[2 * j + 1][0] = q[2]; bf[2 * j + 1][1] = q[3];
            }
#pragma unroll
            for (int f = 0; f < 4; f++)
#pragma unroll
                for (int g = 0; g < 8; g++)
                    mma16816(acc[f][g], ah[f], bf[g]);
        }
        __syncthreads();
    }

    // ---- epilogue ----
    const float* bptr = bias + (size_t)z * NB + nt * BNT;
#pragma unroll
    for (int f = 0; f < 4; f++) {
#pragma unroll
        for (int h = 0; h < 2; h++) {
            const int mg = mt * BMT + m0 + f * 16 + (lane >> 2) + 8 * h;
            if (mg < cnt) {
                const size_t rowg = (size_t)z * CAP + mg;
#pragma unroll
                for (int g = 0; g < 8; g++) {
                    const int nc = n0 + g * 8 + (lane & 3) * 2;
                    float v0 = acc[f][g][2 * h + 0] + __ldg(bptr + nc);
                    float v1 = acc[f][g][2 * h + 1] + __ldg(bptr + nc + 1);
                    if (MODE == 1) {
                        v0 = 0.5f * v0 * (1.0f + erff(v0 * 0.70710678118654752f));
                        v1 = 0.5f * v1 * (1.0f + erff(v1 * 0.70710678118654752f));
                        __half2 hv = __floats2half2_rn(v0, v1);
                        *(unsigned*)(g_Hh + rowg * HDIM + nt * BNT + nc) = *(unsigned*)&hv;
                    } else {
                        *(float2*)(g_F + rowg * DDIM + nt * BNT + nc) = make_float2(v0, v1);
                    }
                }
            }
        }
    }
#undef LOADC
}

__global__ void final_kernel(const float* __restrict__ x, float* __restrict__ out) {
    int idx = blockIdx.x * blockDim.x + threadIdx.x;
    int n = idx >> 8, c = idx & 255;
    float4 xv = ((const float4*)x)[idx];
    int p0 = g_pos[n * 2], p1 = g_pos[n * 2 + 1];
    float gg0 = g_gate[n * 2], gg1 = g_gate[n * 2 + 1];
    const float4* F4 = (const float4*)g_F;
    float4 f0 = F4[(size_t)p0 * 256 + c];
    float4 f1 = F4[(size_t)p1 * 256 + c];
    ((float4*)out)[idx] = make_float4(xv.x + gg0 * f0.x + gg1 * f1.x,
                                      xv.y + gg0 * f0.y + gg1 * f1.y,
                                      xv.z + gg0 * f0.z + gg1 * f1.z,
                                      xv.w + gg0 * f0.w + gg1 * f1.w);
}

// ---------------- launch ----------------
extern "C" void kernel_launch(void* const* d_in, const int* in_sizes, int n_in,
                              void* d_out, int out_size) {
    const float* x    = (const float*)d_in[0];
    const float* Wp   = (const float*)d_in[1];
    const float* bp   = (const float*)d_in[2];
    const float* sim  = (const float*)d_in[3];
    const float* temp = (const float*)d_in[4];
    const float* W1   = (const float*)d_in[5];
    const float* b1   = (const float*)d_in[6];
    const float* W2   = (const float*)d_in[7];
    const float* b2   = (const float*)d_in[8];
    float* out = (float*)d_out;

    // device addresses for any symbol passed as a HOST-side kernel argument
    void *pP = nullptr, *pw1 = nullptr, *pw2 = nullptr;
    cudaGetSymbolAddress(&pP, g_P);
    cudaGetSymbolAddress(&pw1, g_w1t);
    cudaGetSymbolAddress(&pw2, g_w2t);

    init_kernel<<<1, 32>>>();
    simn_kernel<<<1, 32>>>(sim);
    gemm_p<<<dim3(PROJD / 128, NTOK / 128), 256>>>(x, Wp, bp, (float*)pP);
    gating_kernel<<<(NTOK * 32) / 256, 256>>>((const float*)pP, temp);

    conv_x_kernel<<<(NTOK * DDIM / 4) / 256, 256>>>(x, NTOK * DDIM / 4);
    conv_wt_kernel<<<dim3(HDIM / 32, DDIM / 32, NEXP), dim3(32, 8)>>>(W1, (__half*)pw1, DDIM, HDIM);
    conv_wt_kernel<<<dim3(DDIM / 32, HDIM / 32, NEXP), dim3(32, 8)>>>(W2, (__half*)pw2, HDIM, DDIM);

    moe_mma<1><<<dim3(HDIM / BNT, CAP / BMT, NEXP), 256>>>(b1);
    moe_mma<2><<<dim3(DDIM / BNT, CAP / BMT, NEXP), 256>>>(b2);

    final_kernel<<<(NTOK * DDIM / 4) / 256, 256>>>(x, out);
}

// round 12
// speedup vs baseline: 5.7673x; 1.1976x over previous
#include <cuda_runtime.h>
#include <cuda_fp16.h>
#include <math.h>

#define NTOK 16384
#define DDIM 1024
#define HDIM 4096
#define NEXP 8
#define PROJD 256
#define CAP 12288
#define CLAMP_MAXV 4.605170185988091f

#define BMT 256
#define BNT 128
#define BKT 64
#define A_BYTES 32768        /* 256 rows * 128B */
#define B_BYTES 16384        /* 128 rows * 128B */
#define OFF_B A_BYTES
#define STAGE (A_BYTES + B_BYTES)   /* 49152 */
#define SMEM_DYN (2 * STAGE)        /* 98304 */

// ---------------- device scratch ----------------
__device__ float g_P[NTOK * PROJD];
__device__ float g_simn[PROJD * NEXP];
__device__ int   g_perm[NEXP * CAP];
__device__ int   g_pos[NTOK * 2];
__device__ float g_gate[NTOK * 2];
__device__ int   g_cursor[NEXP];
__device__ __half g_xh[(size_t)NTOK * DDIM];
__device__ __half g_w1t[(size_t)NEXP * HDIM * DDIM];   // [E][H][D]
__device__ __half g_w2t[(size_t)NEXP * DDIM * HDIM];   // [E][D][H]
__device__ __half g_Hh[(size_t)NEXP * CAP * HDIM];
__device__ float g_F[(size_t)NEXP * CAP * DDIM];

// ---------------- helpers ----------------
__device__ __forceinline__ unsigned smem_u32(const void* p) {
    unsigned a;
    asm("{ .reg .u64 t; cvta.to.shared.u64 t, %1; cvt.u32.u64 %0, t; }" : "=r"(a) : "l"(p));
    return a;
}
#define CPA(dst, src) asm volatile("cp.async.cg.shared.global [%0], [%1], 16;" :: "r"(dst), "l"(src))
#define CPA_COMMIT()  asm volatile("cp.async.commit_group;" ::: "memory")
#define CPA_WAIT1()   asm volatile("cp.async.wait_group 1;" ::: "memory")
#define CPA_WAIT0()   asm volatile("cp.async.wait_group 0;" ::: "memory")
#define LDSM4(R, A) asm volatile("ldmatrix.sync.aligned.m8n8.x4.shared.b16 {%0,%1,%2,%3}, [%4];" \
    : "=r"((R)[0]), "=r"((R)[1]), "=r"((R)[2]), "=r"((R)[3]) : "r"(A))

__device__ __forceinline__ void mma16816(float* c, const unsigned* a, const unsigned* b) {
    asm volatile(
        "mma.sync.aligned.m16n8k16.row.col.f32.f16.f16.f32 "
        "{%0,%1,%2,%3}, {%4,%5,%6,%7}, {%8,%9}, {%0,%1,%2,%3};"
        : "+f"(c[0]), "+f"(c[1]), "+f"(c[2]), "+f"(c[3])
        : "r"(a[0]), "r"(a[1]), "r"(a[2]), "r"(a[3]), "r"(b[0]), "r"(b[1]));
}
// 64 fp16 per row = 128B line; 16B chunks 0..7, chunk XOR'd by row -> conflict-free
// for 8-row ldmatrix (8 distinct chunk slots across any 8 consecutive rows)
__device__ __forceinline__ unsigned swa(int r, int ch) {
    return (unsigned)(r * 128 + ((ch ^ (r & 7)) << 4));
}

// ---------------- small kernels ----------------
__global__ void init_kernel() { if (threadIdx.x < NEXP) g_cursor[threadIdx.x] = 0; }

__global__ void simn_kernel(const float* __restrict__ sim) {
    int e = threadIdx.x;
    if (e < NEXP) {
        float s = 0.f;
        for (int j = 0; j < PROJD; j++) { float v = sim[j * NEXP + e]; s += v * v; }
        float inv = 1.f / fmaxf(sqrtf(s), 1e-12f);
        for (int j = 0; j < PROJD; j++) g_simn[j * NEXP + e] = sim[j * NEXP + e] * inv;
    }
}

__global__ void gating_kernel(const float* __restrict__ P, const float* __restrict__ temp) {
    __shared__ float ssim[PROJD * NEXP];
    for (int i = threadIdx.x; i < PROJD * NEXP; i += blockDim.x) ssim[i] = g_simn[i];
    __syncthreads();
    int tok = (blockIdx.x * blockDim.x + threadIdx.x) >> 5;
    int lane = threadIdx.x & 31;
    if (tok >= NTOK) return;
    const float* row = P + (size_t)tok * PROJD;
    float dot[NEXP];
#pragma unroll
    for (int e = 0; e < NEXP; e++) dot[e] = 0.f;
    float ss = 0.f;
#pragma unroll
    for (int i = 0; i < PROJD / 32; i++) {
        float p = row[lane + 32 * i];
        ss += p * p;
        const float* sr = ssim + (lane + 32 * i) * NEXP;
#pragma unroll
        for (int e = 0; e < NEXP; e++) dot[e] += p * sr[e];
    }
#pragma unroll
    for (int off = 16; off; off >>= 1) {
        ss += __shfl_down_sync(0xffffffffu, ss, off);
#pragma unroll
        for (int e = 0; e < NEXP; e++) dot[e] += __shfl_down_sync(0xffffffffu, dot[e], off);
    }
    if (lane == 0) {
        float scale = expf(fminf(temp[0], CLAMP_MAXV));
        float inv = 1.f / fmaxf(sqrtf(ss), 1e-12f);
        float lg[NEXP];
#pragma unroll
        for (int e = 0; e < NEXP; e++) lg[e] = dot[e] * inv * scale;
        int e0 = 0;
#pragma unroll
        for (int e = 1; e < NEXP; e++) if (lg[e] > lg[e0]) e0 = e;
        int e1 = (e0 == 0) ? 1 : 0;
#pragma unroll
        for (int e = 0; e < NEXP; e++) if (e != e0 && lg[e] > lg[e1]) e1 = e;
        float ex = expf(lg[e1] - lg[e0]);
        float den = 1.f + ex;
        int p0 = atomicAdd(&g_cursor[e0], 1); p0 = min(p0, CAP - 1);
        g_perm[e0 * CAP + p0] = tok;
        g_pos[tok * 2 + 0] = e0 * CAP + p0;
        g_gate[tok * 2 + 0] = 1.f / den;
        int p1 = atomicAdd(&g_cursor[e1], 1); p1 = min(p1, CAP - 1);
        g_perm[e1 * CAP + p1] = tok;
        g_pos[tok * 2 + 1] = e1 * CAP + p1;
        g_gate[tok * 2 + 1] = ex / den;
    }
}

__global__ void conv_x_kernel(const float* __restrict__ src, int n4) {
    int i = blockIdx.x * blockDim.x + threadIdx.x;
    if (i >= n4) return;
    float4 v = ((const float4*)src)[i];
    __half2 a = __floats2half2_rn(v.x, v.y);
    __half2 b = __floats2half2_rn(v.z, v.w);
    ((uint2*)g_xh)[i] = make_uint2(*(unsigned*)&a, *(unsigned*)&b);
}

// W [E][R][C] fp32 -> T [E][C][R] fp16  (T must be a cudaGetSymbolAddress pointer!)
__global__ void conv_wt_kernel(const float* __restrict__ W, __half* __restrict__ T, int R, int C) {
    __shared__ float tile[32][33];
    int e = blockIdx.z, r0 = blockIdx.y * 32, c0 = blockIdx.x * 32;
    const float* Wp = W + (size_t)e * R * C;
    for (int i = threadIdx.y; i < 32; i += 8)
        tile[i][threadIdx.x] = Wp[(size_t)(r0 + i) * C + c0 + threadIdx.x];
    __syncthreads();
    for (int i = threadIdx.y; i < 32; i += 8)
        T[((size_t)e * C + c0 + i) * R + r0 + threadIdx.x] = __float2half_rn(tile[threadIdx.x][i]);
}

// fp32 SGEMM for gating projection (exact selection)
__global__ __launch_bounds__(256, 2)
void gemm_p(const float* __restrict__ A, const float* __restrict__ Bw,
            const float* __restrict__ bias, float* __restrict__ C) {
    const int K = DDIM, N = PROJD;
    const int mt = blockIdx.y, nt = blockIdx.x;
    __shared__ float As[8][128], Bs[8][128];
    const int tid = threadIdx.x;
    const int aRow = tid >> 1, aK = (tid & 1) * 4;
    const int bK = tid >> 5, bN = (tid & 31) * 4;
    const float* aPtr = A + (size_t)(mt * 128 + aRow) * K + aK;
    const float* bPtr = Bw + (size_t)bK * N + nt * 128 + bN;
    const int tr = tid >> 4, tc = tid & 15;
    float acc[8][8];
#pragma unroll
    for (int i = 0; i < 8; i++)
#pragma unroll
        for (int j = 0; j < 8; j++) acc[i][j] = 0.f;
    float4 ra = *(const float4*)aPtr;
    float4 rb = *(const float4*)bPtr;
    for (int kt = 0; kt < K / 8; kt++) {
        As[aK][aRow] = ra.x; As[aK + 1][aRow] = ra.y; As[aK + 2][aRow] = ra.z; As[aK + 3][aRow] = ra.w;
        *(float4*)&Bs[bK][bN] = rb;
        __syncthreads();
        if (kt + 1 < K / 8) {
            ra = *(const float4*)(aPtr + (size_t)(kt + 1) * 8);
            rb = *(const float4*)(bPtr + (size_t)(kt + 1) * 8 * N);
        }
#pragma unroll
        for (int k = 0; k < 8; k++) {
            float4 a0 = *(const float4*)&As[k][tr * 8];
            float4 a1 = *(const float4*)&As[k][tr * 8 + 4];
            float4 b0 = *(const float4*)&Bs[k][tc * 8];
            float4 b1 = *(const float4*)&Bs[k][tc * 8 + 4];
            float ar[8] = {a0.x, a0.y, a0.z, a0.w, a1.x, a1.y, a1.z, a1.w};
            float br[8] = {b0.x, b0.y, b0.z, b0.w, b1.x, b1.y, b1.z, b1.w};
#pragma unroll
            for (int i = 0; i < 8; i++)
#pragma unroll
                for (int j = 0; j < 8; j++) acc[i][j] += ar[i] * br[j];
        }
        __syncthreads();
    }
#pragma unroll
    for (int i = 0; i < 8; i++) {
        float* cp = C + (size_t)(mt * 128 + tr * 8 + i) * N + nt * 128 + tc * 8;
#pragma unroll
        for (int j = 0; j < 8; j++) cp[j] = acc[i][j] + bias[nt * 128 + tc * 8 + j];
    }
}

// ---------------- HMMA grouped GEMM (fp16 single-pass, fp32 acc, BKT=64, 96KB dyn smem) ----------------
// MODE 1: H = gelu(x[perm] @ W1t^T + b1) -> fp16   MODE 2: F = H @ W2t^T + b2 -> fp32
template <int MODE>
__global__ void __launch_bounds__(256)
moe_mma(const float* __restrict__ bias) {
    constexpr int K  = (MODE == 1) ? DDIM : HDIM;
    constexpr int NB = (MODE == 1) ? HDIM : DDIM;
    constexpr int NK = K / BKT;
    const int z = blockIdx.z, mt = blockIdx.y, nt = blockIdx.x;
    const int cnt = min(g_cursor[z], CAP);
    if (mt * BMT >= cnt) return;

    extern __shared__ __align__(128) char smem[];
    const unsigned sb = smem_u32(smem);
    const int tid = threadIdx.x, wid = tid >> 5, lane = tid & 31;

    // ---- load mapping: thread -> row tid>>2 (A: and +64,+128,+192; B: +64), chunk pair (tid&3)*2 ----
    const int lrow = tid >> 2;
    const int chb = (tid & 3) * 2;           // chunk base 0,2,4,6
    size_t aOff[4];
#pragma unroll
    for (int i = 0; i < 4; i++) {
        int r = min(mt * BMT + lrow + 64 * i, cnt - 1);
        if (MODE == 1) aOff[i] = (size_t)g_perm[z * CAP + r] * DDIM;
        else           aOff[i] = ((size_t)z * CAP + r) * (size_t)HDIM;
    }
    const size_t bOff0 = ((size_t)z * NB + nt * BNT + lrow) * (size_t)K;
    const size_t bOff1 = ((size_t)z * NB + nt * BNT + lrow + 64) * (size_t)K;
    const __half* gA = (MODE == 1) ? g_xh : g_Hh;
    const __half* gB = (MODE == 1) ? g_w1t : g_w2t;

#define LOADC(cc, ss) do { \
        const unsigned st_ = sb + (ss) * STAGE; \
        const int ke_ = (cc) * BKT + chb * 8; \
        _Pragma("unroll") \
        for (int i = 0; i < 4; i++) { \
            CPA(st_ + swa(lrow + 64 * i, chb),     gA + aOff[i] + ke_); \
            CPA(st_ + swa(lrow + 64 * i, chb + 1), gA + aOff[i] + ke_ + 8); \
        } \
        CPA(st_ + OFF_B + swa(lrow, chb),          gB + bOff0 + ke_); \
        CPA(st_ + OFF_B + swa(lrow, chb + 1),      gB + bOff0 + ke_ + 8); \
        CPA(st_ + OFF_B + swa(lrow + 64, chb),     gB + bOff1 + ke_); \
        CPA(st_ + OFF_B + swa(lrow + 64, chb + 1), gB + bOff1 + ke_ + 8); \
        CPA_COMMIT(); \
    } while (0)

    // ---- compute mapping: 8 warps as 4(M) x 2(N); warp tile 64x64 ----
    const int m0 = (wid & 3) * 64;
    const int n0 = (wid >> 2) * 64;
    const int rA = ((lane >> 3) & 1) * 8 + (lane & 7);
    const int cA = lane >> 4;
    const int rB = (lane >> 4) * 8 + (lane & 7);
    const int cB = (lane >> 3) & 1;

    float acc[4][8][4];
#pragma unroll
    for (int f = 0; f < 4; f++)
#pragma unroll
        for (int g = 0; g < 8; g++)
#pragma unroll
            for (int q = 0; q < 4; q++) acc[f][g][q] = 0.f;

    LOADC(0, 0);
    for (int c = 0; c < NK; c++) {
        const int s = c & 1;
        if (c + 1 < NK) { LOADC(c + 1, s ^ 1); CPA_WAIT1(); }
        else CPA_WAIT0();
        __syncthreads();
        const unsigned st = sb + s * STAGE;
#pragma unroll
        for (int kk = 0; kk < 4; kk++) {
            unsigned ah[4][4], bf[8][2];
#pragma unroll
            for (int f = 0; f < 4; f++)
                LDSM4(ah[f], st + swa(m0 + f * 16 + rA, kk * 2 + cA));
#pragma unroll
            for (int j = 0; j < 4; j++) {
                unsigned q[4];
                LDSM4(q, st + OFF_B + swa(n0 + j * 16 + rB, kk * 2 + cB));
                bf[2 * j][0] = q[0]; bf[2 * j][1] = q[1];
                bf[2 * j + 1][0] = q[2]; bf[2 * j + 1][1] = q[3];
            }
#pragma unroll
            for (int f = 0; f < 4; f++)
#pragma unroll
                for (int g = 0; g < 8; g++)
                    mma16816(acc[f][g], ah[f], bf[g]);
        }
        __syncthreads();
    }

    // ---- epilogue ----
    const float* bptr = bias + (size_t)z * NB + nt * BNT;
#pragma unroll
    for (int f = 0; f < 4; f++) {
#pragma unroll
        for (int h = 0; h < 2; h++) {
            const int mg = mt * BMT + m0 + f * 16 + (lane >> 2) + 8 * h;
            if (mg < cnt) {
                const size_t rowg = (size_t)z * CAP + mg;
#pragma unroll
                for (int g = 0; g < 8; g++) {
                    const int nc = n0 + g * 8 + (lane & 3) * 2;
                    float v0 = acc[f][g][2 * h + 0] + __ldg(bptr + nc);
                    float v1 = acc[f][g][2 * h + 1] + __ldg(bptr + nc + 1);
                    if (MODE == 1) {
                        v0 = 0.5f * v0 * (1.0f + erff(v0 * 0.70710678118654752f));
                        v1 = 0.5f * v1 * (1.0f + erff(v1 * 0.70710678118654752f));
                        __half2 hv = __floats2half2_rn(v0, v1);
                        *(unsigned*)(g_Hh + rowg * HDIM + nt * BNT + nc) = *(unsigned*)&hv;
                    } else {
                        *(float2*)(g_F + rowg * DDIM + nt * BNT + nc) = make_float2(v0, v1);
                    }
                }
            }
        }
    }
#undef LOADC
}

__global__ void final_kernel(const float* __restrict__ x, float* __restrict__ out) {
    int idx = blockIdx.x * blockDim.x + threadIdx.x;
    int n = idx >> 8, c = idx & 255;
    float4 xv = ((const float4*)x)[idx];
    int p0 = g_pos[n * 2], p1 = g_pos[n * 2 + 1];
    float gg0 = g_gate[n * 2], gg1 = g_gate[n * 2 + 1];
    const float4* F4 = (const float4*)g_F;
    float4 f0 = F4[(size_t)p0 * 256 + c];
    float4 f1 = F4[(size_t)p1 * 256 + c];
    ((float4*)out)[idx] = make_float4(xv.x + gg0 * f0.x + gg1 * f1.x,
                                      xv.y + gg0 * f0.y + gg1 * f1.y,
                                      xv.z + gg0 * f0.z + gg1 * f1.z,
                                      xv.w + gg0 * f0.w + gg1 * f1.w);
}

// ---------------- launch ----------------
extern "C" void kernel_launch(void* const* d_in, const int* in_sizes, int n_in,
                              void* d_out, int out_size) {
    const float* x    = (const float*)d_in[0];
    const float* Wp   = (const float*)d_in[1];
    const float* bp   = (const float*)d_in[2];
    const float* sim  = (const float*)d_in[3];
    const float* temp = (const float*)d_in[4];
    const float* W1   = (const float*)d_in[5];
    const float* b1   = (const float*)d_in[6];
    const float* W2   = (const float*)d_in[7];
    const float* b2   = (const float*)d_in[8];
    float* out = (float*)d_out;

    cudaFuncSetAttribute(moe_mma<1>, cudaFuncAttributeMaxDynamicSharedMemorySize, SMEM_DYN);
    cudaFuncSetAttribute(moe_mma<2>, cudaFuncAttributeMaxDynamicSharedMemorySize, SMEM_DYN);

    // device addresses for any symbol passed as a HOST-side kernel argument
    void *pP = nullptr, *pw1 = nullptr, *pw2 = nullptr;
    cudaGetSymbolAddress(&pP, g_P);
    cudaGetSymbolAddress(&pw1, g_w1t);
    cudaGetSymbolAddress(&pw2, g_w2t);

    init_kernel<<<1, 32>>>();
    simn_kernel<<<1, 32>>>(sim);
    gemm_p<<<dim3(PROJD / 128, NTOK / 128), 256>>>(x, Wp, bp, (float*)pP);
    gating_kernel<<<(NTOK * 32) / 256, 256>>>((const float*)pP, temp);

    conv_x_kernel<<<(NTOK * DDIM / 4) / 256, 256>>>(x, NTOK * DDIM / 4);
    conv_wt_kernel<<<dim3(HDIM / 32, DDIM / 32, NEXP), dim3(32, 8)>>>(W1, (__half*)pw1, DDIM, HDIM);
    conv_wt_kernel<<<dim3(DDIM / 32, HDIM / 32, NEXP), dim3(32, 8)>>>(W2, (__half*)pw2, HDIM, DDIM);

    moe_mma<1><<<dim3(HDIM / BNT, CAP / BMT, NEXP), 256, SMEM_DYN>>>(b1);
    moe_mma<2><<<dim3(DDIM / BNT, CAP / BMT, NEXP), 256, SMEM_DYN>>>(b2);

    final_kernel<<<(NTOK * DDIM / 4) / 256, 256>>>(x, out);
}